// round 2
// baseline (speedup 1.0000x reference)
#include <cuda_runtime.h>
#include <math.h>

// MoEGate: x[16384,2048] @ W^T[2048,64] -> softmax -> top2 (+norm) -> seq aux loss
// Output layout (float32): [ indices(16384*2) | weights(16384*2) | aux_loss(1) ]

#define D_DIM    2048
#define E_EXP    64
#define TM       128          // tokens per block
#define KC       32           // K chunk
#define NT       256          // threads per block
#define NTOK     16384
#define NBLK     (NTOK / TM)  // 128
#define NCHUNK   (D_DIM / KC) // 64
#define SEQ      4096
#define BATCH    4
#define TILES_PER_B (NBLK / BATCH) // 32
#define ALPHA    0.01f
#define XS_STRIDE 68          // floats per token row (dup pairs), 272B: 16B aligned, bank-safe
#define WS_STRIDE 68

typedef unsigned long long u64;

// Deterministic scratch (every slot rewritten every launch)
__device__ float    g_scores_part[NBLK][E_EXP];
__device__ int      g_cnt_part[NBLK][E_EXP];
__device__ unsigned g_done = 0;   // reset to 0 by last block each launch

__device__ __forceinline__ void ffma2(u64& d, u64 a, u64 b) {
    asm volatile("fma.rn.f32x2 %0, %1, %2, %0;" : "+l"(d) : "l"(a), "l"(b));
}
__device__ __forceinline__ void unpack2(u64 v, float& lo, float& hi) {
    unsigned a, b;
    asm("mov.b64 {%0, %1}, %2;" : "=r"(a), "=r"(b) : "l"(v));
    lo = __uint_as_float(a); hi = __uint_as_float(b);
}

struct P1 {
    float xs[TM][XS_STRIDE];   // token t, entries [2k],[2k+1] = dup x[t][k]  (34816 B)
    float ws[KC][WS_STRIDE];   // w[k][e] at ws[k][e]                         ( 8704 B)
};
struct P2 {
    float lg[TM][E_EXP + 1];   // logits -> exp -> scores
    float red[2][TM];          // max/sum halves; reused as contrib[4][64] in finalize
    int   cnt[E_EXP];
};
union SmU { P1 p1; P2 p2; };

__global__ void __launch_bounds__(NT, 1)
moe_gate_kernel(const float* __restrict__ x, const float* __restrict__ w,
                float* __restrict__ out)
{
    __shared__ __align__(16) SmU sm;
    __shared__ bool s_last;
    const int tid  = threadIdx.x;
    const int blk  = blockIdx.x;
    const int ex_g = tid & 7;   // experts ex_g*8 .. +7 (4 f32x2 pairs)
    const int tp_g = tid >> 3;  // tokens  tp_g*4 .. +3
    const int tok0 = blk * TM;

    u64 acc[4][4];
    #pragma unroll
    for (int j = 0; j < 4; j++)
        #pragma unroll
        for (int p = 0; p < 4; p++) acc[j][p] = 0ull;

    float4 xr[4], wr[2];

    // ---- stage chunk 0 ----
    #pragma unroll
    for (int i = 0; i < 4; i++) {
        int idx = i * NT + tid;
        int t = idx >> 3, f4 = idx & 7;
        xr[i] = *(const float4*)(x + (size_t)(tok0 + t) * D_DIM + f4 * 4);
    }
    #pragma unroll
    for (int i = 0; i < 2; i++) {
        int idx = i * NT + tid;
        int e = idx >> 3, f4 = idx & 7;
        wr[i] = *(const float4*)(w + (size_t)e * D_DIM + f4 * 4);
    }

    for (int c = 0; c < NCHUNK; c++) {
        __syncthreads();
        // ---- commit staged chunk (x duplicated, w transposed) ----
        #pragma unroll
        for (int i = 0; i < 4; i++) {
            int idx = i * NT + tid;
            int t = idx >> 3, f4 = idx & 7;
            float4 v = xr[i];
            float4 a = make_float4(v.x, v.x, v.y, v.y);
            float4 b = make_float4(v.z, v.z, v.w, v.w);
            *(float4*)&sm.p1.xs[t][8 * f4 + 0] = a;
            *(float4*)&sm.p1.xs[t][8 * f4 + 4] = b;
        }
        #pragma unroll
        for (int i = 0; i < 2; i++) {
            int idx = i * NT + tid;
            int e = idx >> 3, f4 = idx & 7;
            float4 v = wr[i];
            sm.p1.ws[f4 * 4 + 0][e] = v.x;
            sm.p1.ws[f4 * 4 + 1][e] = v.y;
            sm.p1.ws[f4 * 4 + 2][e] = v.z;
            sm.p1.ws[f4 * 4 + 3][e] = v.w;
        }
        __syncthreads();

        // ---- prefetch next chunk ----
        if (c + 1 < NCHUNK) {
            const int ko = (c + 1) * KC;
            #pragma unroll
            for (int i = 0; i < 4; i++) {
                int idx = i * NT + tid;
                int t = idx >> 3, f4 = idx & 7;
                xr[i] = *(const float4*)(x + (size_t)(tok0 + t) * D_DIM + ko + f4 * 4);
            }
            #pragma unroll
            for (int i = 0; i < 2; i++) {
                int idx = i * NT + tid;
                int e = idx >> 3, f4 = idx & 7;
                wr[i] = *(const float4*)(w + (size_t)e * D_DIM + ko + f4 * 4);
            }
        }

        // ---- compute: 4 tok x 8 exp per thread; experts f32x2-paired ----
        #pragma unroll 8
        for (int k = 0; k < KC; k++) {
            u64 xv[4];
            #pragma unroll
            for (int j = 0; j < 4; j++)
                xv[j] = *(const u64*)&sm.p1.xs[tp_g * 4 + j][2 * k];
            float4 w0 = *(const float4*)&sm.p1.ws[k][ex_g * 8];
            float4 w1 = *(const float4*)&sm.p1.ws[k][ex_g * 8 + 4];
            u64 wv[4];
            wv[0] = ((const u64*)&w0)[0];
            wv[1] = ((const u64*)&w0)[1];
            wv[2] = ((const u64*)&w1)[0];
            wv[3] = ((const u64*)&w1)[1];
            #pragma unroll
            for (int j = 0; j < 4; j++)
                #pragma unroll
                for (int p = 0; p < 4; p++) ffma2(acc[j][p], xv[j], wv[p]);
        }
    }

    __syncthreads();  // done with p1 smem

    // ---- spill logits ----
    #pragma unroll
    for (int j = 0; j < 4; j++)
        #pragma unroll
        for (int p = 0; p < 4; p++) {
            float lo, hi; unpack2(acc[j][p], lo, hi);
            int t = tp_g * 4 + j, e = ex_g * 8 + 2 * p;
            sm.p2.lg[t][e + 0] = lo;
            sm.p2.lg[t][e + 1] = hi;
        }
    if (tid < E_EXP) sm.p2.cnt[tid] = 0;
    __syncthreads();

    // ---- softmax: 2 threads per token (32 experts each) ----
    const int tt = tid & 127, hf = tid >> 7;
    float* row = sm.p2.lg[tt];
    const int e0 = hf * 32;
    {
        float mx = row[e0];
        #pragma unroll
        for (int e = 1; e < 32; e++) mx = fmaxf(mx, row[e0 + e]);
        sm.p2.red[hf][tt] = mx;
    }
    __syncthreads();
    {
        float mx = fmaxf(sm.p2.red[0][tt], sm.p2.red[1][tt]);
        float s = 0.f;
        #pragma unroll
        for (int e = 0; e < 32; e++) {
            float ex = __expf(row[e0 + e] - mx);
            row[e0 + e] = ex;
            s += ex;
        }
        __syncthreads();                 // everyone done reading red as maxes
        sm.p2.red[hf][tt] = s;
    }
    __syncthreads();
    {
        float Z = sm.p2.red[0][tt] + sm.p2.red[1][tt];
        float inv = 1.0f / Z;
        #pragma unroll
        for (int e = 0; e < 32; e++) row[e0 + e] *= inv;
    }
    __syncthreads();

    // ---- top2 + outputs (1 thread : 1 token) ----
    if (tid < TM) {
        float* r = sm.p2.lg[tid];
        float v1 = -1.f, v2 = -1.f; int i1 = 0, i2 = 0;
        #pragma unroll
        for (int e = 0; e < E_EXP; e++) {
            float s = r[e];
            if (s > v1)      { v2 = v1; i2 = i1; v1 = s; i1 = e; }
            else if (s > v2) { v2 = s;  i2 = e; }
        }
        float denom = v1 + v2 + 1e-20f;
        float w1 = v1 / denom, w2 = v2 / denom;
        int gt = tok0 + tid;
        out[gt * 2 + 0] = (float)i1;
        out[gt * 2 + 1] = (float)i2;
        out[2 * NTOK + gt * 2 + 0] = w1;
        out[2 * NTOK + gt * 2 + 1] = w2;
        atomicAdd(&sm.p2.cnt[i1], 1);
        atomicAdd(&sm.p2.cnt[i2], 1);
    }
    __syncthreads();

    // ---- deterministic per-block partials ----
    if (tid < E_EXP) {
        float s = 0.f;
        for (int t = 0; t < TM; t++) s += sm.p2.lg[t][tid];
        g_scores_part[blk][tid] = s;
        g_cnt_part[blk][tid]    = sm.p2.cnt[tid];
    }

    // ---- last block performs the finalize (deterministic reduction) ----
    __threadfence();
    if (tid == 0) s_last = (atomicAdd(&g_done, 1) == NBLK - 1);
    __syncthreads();
    if (!s_last) return;
    __threadfence();  // acquire: all blocks' partials now visible

    float* contrib = &sm.p2.red[0][0];  // 256 floats = [BATCH][E_EXP]
    if (tid < E_EXP) {
        int e = tid;
        for (int b = 0; b < BATCH; b++) {
            int cntv = 0; float ss = 0.f;
            for (int t = 0; t < TILES_PER_B; t++) {
                cntv += g_cnt_part[b * TILES_PER_B + t][e];
                ss   += g_scores_part[b * TILES_PER_B + t][e];
            }
            float ce = (float)cntv * ((float)E_EXP / (float)(SEQ * 2));
            float ms = ss / (float)SEQ;
            contrib[b * E_EXP + e] = ce * ms;
        }
    }
    __syncthreads();
    if (tid == 0) {
        float loss = 0.f;
        for (int b = 0; b < BATCH; b++) {
            float r = 0.f;
            for (int e = 0; e < E_EXP; e++) r += contrib[b * E_EXP + e];
            loss += r;
        }
        out[4 * NTOK] = loss / (float)BATCH * ALPHA;
        g_done = 0;  // reset for next graph replay
    }
}

extern "C" void kernel_launch(void* const* d_in, const int* in_sizes, int n_in,
                              void* d_out, int out_size)
{
    const float* x = (const float*)d_in[0];  // [4,4096,2048] fp32
    const float* w = (const float*)d_in[1];  // [64,2048] fp32
    float* out = (float*)d_out;
    moe_gate_kernel<<<NBLK, NT>>>(x, w, out);
}